// round 13
// baseline (speedup 1.0000x reference)
#include <cuda_runtime.h>
#include <cuda_bf16.h>
#include <cstdint>

#define GNX 512
#define GNY 512
#define GP (GNX * GNY)            // 262144 pillars
#define GB 4
#define GNPTS 100000
#define GC 64
#define TILE_P 64                 // pillars per tile (one gather block)
#define TILES_PER_B (GP / TILE_P) // 4096
#define NTILES (GB * TILES_PER_B) // 16384
#define CAP 64                    // bucket capacity per tile (mean load 24)
#define NPTS_TOTAL (GB * GNPTS)   // 400000
#define OVF_MAX 4096

// Buckets: 16384 tiles * 64 entries * 4B = 4 MB (L2-resident for gather).
// Cursors zeroed at module load, re-zeroed by gather each call.
// Overflow counter re-zeroed by spill each call.
__device__ int      g_cursor[NTILES];
__device__ unsigned g_list[(size_t)NTILES * CAP];
__device__ int      g_ovf_cnt;
__device__ uint2    g_ovf[OVF_MAX];

// ---------------------------------------------------------------------------
// K1: fill buckets. 4 points/thread via int4 (4 independent ATOMG chains).
// entry = (pillar & 63) << 20 | global_point_id  (400000 < 2^20).
// Indices are int32 on the wire (JAX x64-off). GNPTS % 4 == 0.
// ---------------------------------------------------------------------------
__global__ void fill_kernel(const int* __restrict__ indices) {
    int t = blockIdx.x * blockDim.x + threadIdx.x;
    if (t >= NPTS_TOTAL / 4) return;
    int b = (t * 4) / GNPTS;
    int4 p4 = reinterpret_cast<const int4*>(indices)[t];
    int base = b * TILES_PER_B;
    int p[4] = {p4.x, p4.y, p4.z, p4.w};
#pragma unroll
    for (int k = 0; k < 4; k++) {
        if (p[k] >= 0 && p[k] < GP) {
            int tile = base + (p[k] >> 6);
            int pos = atomicAdd(&g_cursor[tile], 1);
            unsigned gid = (unsigned)(t * 4 + k);
            if (pos < CAP) {
                g_list[(size_t)tile * CAP + pos] =
                    ((unsigned)(p[k] & 63) << 20) | gid;
            } else {
                int o = atomicAdd(&g_ovf_cnt, 1);
                if (o < OVF_MAX) g_ovf[o] = make_uint2(gid, (unsigned)p[k]);
            }
        }
    }
}

// ---------------------------------------------------------------------------
// K2: gather + accumulate + write. One block per 64-pillar tile.
// Cursor: block-wide read, BARRIER, then zero (barrier is load-bearing).
// Half-warp per point: 16 lanes read the 256B row as float4 (__ldcs), then
// 4 smem atomicAdds. Channel c is stored in PERMUTED slot
// s(c) = (c&3)*16 + (c>>2), so the atomic for c=4lh+m targets slot 16m+lh:
// with stride 65 (bank = slot + plo mod 32) the 16 lanes of a half hit 16
// DISTINCT banks (the old layout guaranteed 2-way conflicts on every ATOMS).
// The output loop inverts the permutation with free index math.
// ---------------------------------------------------------------------------
__global__ void __launch_bounds__(256) gather_kernel(const float* __restrict__ x,
                                                     float* __restrict__ out) {
    __shared__ float acc[GC][TILE_P + 1];

    int tid  = threadIdx.x;
    int tile = blockIdx.x;

    int cnt = g_cursor[tile];              // block-wide read
    for (int i = tid; i < GC * (TILE_P + 1); i += 256)
        ((float*)acc)[i] = 0.0f;
    __syncthreads();                       // all reads done before the zero
    if (tid == 0) g_cursor[tile] = 0;      // re-zero for next replay
    cnt = min(cnt, CAP);

    int wid  = tid >> 5;
    int lane = tid & 31;
    int half = lane >> 4;        // which point of the pair
    int lh   = lane & 15;        // lane within half-warp

    const unsigned* lst = g_list + (size_t)tile * CAP;
    for (int e0 = wid * 2; e0 < cnt; e0 += 16) {
        int e = e0 + half;
        if (e < cnt) {
            unsigned ent = lst[e];
            unsigned gid = ent & 0xFFFFFu;
            unsigned plo = ent >> 20;
            float4 v = __ldcs(reinterpret_cast<const float4*>(
                                  x + (size_t)gid * GC) + lh);
            // channels 4lh+0..3 -> slots 0*16+lh, 1*16+lh, 2*16+lh, 3*16+lh
            atomicAdd(&acc[lh +  0][plo], v.x);
            atomicAdd(&acc[lh + 16][plo], v.y);
            atomicAdd(&acc[lh + 32][plo], v.z);
            atomicAdd(&acc[lh + 48][plo], v.w);
        }
    }
    __syncthreads();

    int b  = tile / TILES_PER_B;
    int p0 = (tile % TILES_PER_B) << 6;
    float* obase = out + ((size_t)b * GC) * GP + p0;

    for (int i = tid; i < GC * (TILE_P / 4); i += 256) {
        int c = i >> 4;
        int q = (i & 15) << 2;
        int s = ((c & 3) << 4) | (c >> 2);   // slot holding channel c
        float4 v = make_float4(acc[s][q], acc[s][q + 1],
                               acc[s][q + 2], acc[s][q + 3]);
        __stwt(reinterpret_cast<float4*>(obase + (size_t)c * GP + q), v);
    }
}

// ---------------------------------------------------------------------------
// K3: spill — bucket overflow (normally zero entries). Single block, runs
// after gather so atomicAdd into the already-written out is correct.
// Re-zeroes the overflow counter for the next invocation.
// ---------------------------------------------------------------------------
__global__ void spill_kernel(const float* __restrict__ x,
                             float* __restrict__ out) {
    int cnt = g_ovf_cnt;
    if (cnt > OVF_MAX) cnt = OVF_MAX;
    int tid = threadIdx.x;
    for (int w = tid; w < cnt * 16; w += 256) {
        int e  = w >> 4;
        int c4 = (w & 15) << 2;
        uint2 ent = g_ovf[e];
        unsigned gid = ent.x;
        int p = (int)ent.y;
        int b = gid / GNPTS;
        float4 v = *reinterpret_cast<const float4*>(x + (size_t)gid * GC + c4);
        float* o = out + ((size_t)b * GC + c4) * GP + p;
        atomicAdd(o + 0 * (size_t)GP, v.x);
        atomicAdd(o + 1 * (size_t)GP, v.y);
        atomicAdd(o + 2 * (size_t)GP, v.z);
        atomicAdd(o + 3 * (size_t)GP, v.w);
    }
    __syncthreads();
    if (tid == 0) g_ovf_cnt = 0;
}

extern "C" void kernel_launch(void* const* d_in, const int* in_sizes, int n_in,
                              void* d_out, int out_size) {
    const float* x   = (const float*)d_in[0];   // (B, N, C) fp32
    const int*   idx = (const int*)d_in[1];     // (B, N) int32
    float*       out = (float*)d_out;           // (B, C, NX, NY) fp32

    (void)in_sizes; (void)n_in; (void)out_size;

    fill_kernel<<<(NPTS_TOTAL / 4 + 255) / 256, 256>>>(idx);
    gather_kernel<<<NTILES, 256>>>(x, out);
    spill_kernel<<<1, 256>>>(x, out);
}

// round 14
// speedup vs baseline: 1.0727x; 1.0727x over previous
#include <cuda_runtime.h>
#include <cuda_bf16.h>
#include <cstdint>

#define GNX 512
#define GNY 512
#define GP (GNX * GNY)            // 262144 pillars
#define GB 4
#define GNPTS 100000
#define GC 64
#define TILE_P 64                 // pillars per tile (one gather block)
#define TILES_PER_B (GP / TILE_P) // 4096
#define NTILES (GB * TILES_PER_B) // 16384
#define CAP 64                    // bucket capacity per tile (mean load 24)
#define NPTS_TOTAL (GB * GNPTS)   // 400000
#define OVF_MAX 4096

// Buckets: 16384 tiles * 64 entries * 4B = 4 MB (L2-resident for gather).
// Cursors zeroed at module load, re-zeroed by gather each call.
// Overflow counter re-zeroed by spill each call.
__device__ int      g_cursor[NTILES];
__device__ unsigned g_list[(size_t)NTILES * CAP];
__device__ int      g_ovf_cnt;
__device__ uint2    g_ovf[OVF_MAX];

// ---------------------------------------------------------------------------
// K1: fill buckets. 4 points/thread via int4 (4 independent ATOMG chains).
// entry = (pillar & 63) << 20 | global_point_id  (400000 < 2^20).
// Indices are int32 on the wire (JAX x64-off). GNPTS % 4 == 0.
// ---------------------------------------------------------------------------
__global__ void fill_kernel(const int* __restrict__ indices) {
    int t = blockIdx.x * blockDim.x + threadIdx.x;
    if (t >= NPTS_TOTAL / 4) return;
    int b = (t * 4) / GNPTS;
    int4 p4 = reinterpret_cast<const int4*>(indices)[t];
    int base = b * TILES_PER_B;
    int p[4] = {p4.x, p4.y, p4.z, p4.w};
#pragma unroll
    for (int k = 0; k < 4; k++) {
        if (p[k] >= 0 && p[k] < GP) {
            int tile = base + (p[k] >> 6);
            int pos = atomicAdd(&g_cursor[tile], 1);
            unsigned gid = (unsigned)(t * 4 + k);
            if (pos < CAP) {
                g_list[(size_t)tile * CAP + pos] =
                    ((unsigned)(p[k] & 63) << 20) | gid;
            } else {
                int o = atomicAdd(&g_ovf_cnt, 1);
                if (o < OVF_MAX) g_ovf[o] = make_uint2(gid, (unsigned)p[k]);
            }
        }
    }
}

// ---------------------------------------------------------------------------
// K2: gather + accumulate + write. One block per 64-pillar tile.
// Cursor: block-wide read, BARRIER, then zero (barrier is load-bearing).
// Half-warp per point: 16 lanes read the 256B row as float4 (__ldcs, full
// sectors), 4 smem atomicAdds each. SOFTWARE PIPELINED: the next entry's
// list word + row are fetched BEFORE the current entry's atomics, doubling
// load MLP and overlapping ATOMS with DRAM latency.
// acc layout = R11's measured-90.2us version (banking changes proved
// neutral-to-negative on B300's atomic unit — do not re-add permutations).
// ---------------------------------------------------------------------------
__global__ void __launch_bounds__(256) gather_kernel(const float* __restrict__ x,
                                                     float* __restrict__ out) {
    __shared__ float acc[GC][TILE_P + 1];

    int tid  = threadIdx.x;
    int tile = blockIdx.x;

    int cnt = g_cursor[tile];              // block-wide read
    for (int i = tid; i < GC * (TILE_P + 1); i += 256)
        ((float*)acc)[i] = 0.0f;
    __syncthreads();                       // all reads done before the zero
    if (tid == 0) g_cursor[tile] = 0;      // re-zero for next replay
    cnt = min(cnt, CAP);

    int wid  = tid >> 5;
    int lane = tid & 31;
    int half = lane >> 4;        // which point of the pair
    int lh   = lane & 15;        // lane within half-warp

    const unsigned* lst = g_list + (size_t)tile * CAP;

    int e = wid * 2 + half;
    bool valid = e < cnt;
    unsigned ent = 0;
    float4 v = make_float4(0.f, 0.f, 0.f, 0.f);
    if (valid) {
        ent = lst[e];
        v = __ldcs(reinterpret_cast<const float4*>(
                       x + (size_t)(ent & 0xFFFFFu) * GC) + lh);
    }
    while (valid) {
        // prefetch next entry before this entry's atomics
        int en = e + 16;
        bool vn = en < cnt;
        unsigned entn = 0;
        float4 vN = make_float4(0.f, 0.f, 0.f, 0.f);
        if (vn) {
            entn = lst[en];
            vN = __ldcs(reinterpret_cast<const float4*>(
                            x + (size_t)(entn & 0xFFFFFu) * GC) + lh);
        }

        unsigned plo = ent >> 20;
        atomicAdd(&acc[4 * lh + 0][plo], v.x);
        atomicAdd(&acc[4 * lh + 1][plo], v.y);
        atomicAdd(&acc[4 * lh + 2][plo], v.z);
        atomicAdd(&acc[4 * lh + 3][plo], v.w);

        e = en; ent = entn; v = vN; valid = vn;
    }
    __syncthreads();

    int b  = tile / TILES_PER_B;
    int p0 = (tile % TILES_PER_B) << 6;
    float* obase = out + ((size_t)b * GC) * GP + p0;

    for (int i = tid; i < GC * (TILE_P / 4); i += 256) {
        int c = i >> 4;
        int q = (i & 15) << 2;
        float4 v4 = make_float4(acc[c][q], acc[c][q + 1],
                                acc[c][q + 2], acc[c][q + 3]);
        __stwt(reinterpret_cast<float4*>(obase + (size_t)c * GP + q), v4);
    }
}

// ---------------------------------------------------------------------------
// K3: spill — bucket overflow (normally zero entries). Single block, runs
// after gather so atomicAdd into the already-written out is correct.
// Re-zeroes the overflow counter for the next invocation.
// ---------------------------------------------------------------------------
__global__ void spill_kernel(const float* __restrict__ x,
                             float* __restrict__ out) {
    int cnt = g_ovf_cnt;
    if (cnt > OVF_MAX) cnt = OVF_MAX;
    int tid = threadIdx.x;
    for (int w = tid; w < cnt * 16; w += 256) {
        int e  = w >> 4;
        int c4 = (w & 15) << 2;
        uint2 ent = g_ovf[e];
        unsigned gid = ent.x;
        int p = (int)ent.y;
        int b = gid / GNPTS;
        float4 v = *reinterpret_cast<const float4*>(x + (size_t)gid * GC + c4);
        float* o = out + ((size_t)b * GC + c4) * GP + p;
        atomicAdd(o + 0 * (size_t)GP, v.x);
        atomicAdd(o + 1 * (size_t)GP, v.y);
        atomicAdd(o + 2 * (size_t)GP, v.z);
        atomicAdd(o + 3 * (size_t)GP, v.w);
    }
    __syncthreads();
    if (tid == 0) g_ovf_cnt = 0;
}

extern "C" void kernel_launch(void* const* d_in, const int* in_sizes, int n_in,
                              void* d_out, int out_size) {
    const float* x   = (const float*)d_in[0];   // (B, N, C) fp32
    const int*   idx = (const int*)d_in[1];     // (B, N) int32
    float*       out = (float*)d_out;           // (B, C, NX, NY) fp32

    (void)in_sizes; (void)n_in; (void)out_size;

    fill_kernel<<<(NPTS_TOTAL / 4 + 255) / 256, 256>>>(idx);
    gather_kernel<<<NTILES, 256>>>(x, out);
    spill_kernel<<<1, 256>>>(x, out);
}